// round 1
// baseline (speedup 1.0000x reference)
#include <cuda_runtime.h>

#define NB 64
#define NO 10
#define NI 8000
#define ND 16
#define NE 8

#define ITILE 4
#define NTHR 512
#define NSTAGES (NI / ITILE)   // 2000 stages of 4 i's
#define NBLK 592               // grid-stride; ~4 stages per block

// Scratch in device globals (no allocation allowed). Zero-initialized at load;
// squash_kernel re-zeros g_s at the end of every full run, so graph replays
// are deterministic.
__device__ float g_s[NB * NO * ND] = {};
__device__ float g_v[NB * NO * ND] = {};
__device__ float g_vsum[NB * NO * ND] = {};

// One fused pass: recompute u_hat[b,o,i,d] tile-by-tile from W,x staged in
// shared, apply routing weights (uniform for ITER 0, softmax of u_hat.v for
// ITER 1/2), accumulate s[b,o,d] in registers, flush with atomics.
// Thread layout: lane = d (16), group = b (each group covers b and b+32),
// so W is read from shared once per i and reused for all 64 batches.
template <int ITER>
__global__ void __launch_bounds__(NTHR)
pass_kernel(const float* __restrict__ xg, const float* __restrict__ Wg)
{
    // shW layout per (j,o): float4 index qs = e4*16 + d  (conflict-free reads:
    // lanes d=0..15 stride 16B -> one 128B phase per 8 lanes)
    __shared__ float4 shW[ITILE * NO * 32];  // 20 KB
    __shared__ float4 shx[ITILE * NB * 2];   // 8 KB

    const int tid  = threadIdx.x;
    const int lane = tid & 15;   // d
    const int grp  = tid >> 4;   // 0..31
    const int b0 = grp, b1 = grp + 32;

    float vr0[NO], vr1[NO];
    if (ITER >= 1) {
        const float* vin = (ITER == 1) ? g_v : g_vsum;
        #pragma unroll
        for (int o = 0; o < NO; o++) {
            vr0[o] = vin[(b0 * NO + o) * ND + lane];
            vr1[o] = vin[(b1 * NO + o) * ND + lane];
        }
    }

    float acc0[NO], acc1[NO];
    #pragma unroll
    for (int o = 0; o < NO; o++) { acc0[o] = 0.f; acc1[o] = 0.f; }

    const float4* Wf4 = (const float4*)Wg;
    const float4* xf4 = (const float4*)xg;

    for (int st = blockIdx.x; st < NSTAGES; st += NBLK) {
        const int i0 = st * ITILE;
        __syncthreads();
        // Stage W[o, i0..i0+3, :, :]  (ITILE*10*32 float4 = 1280 f4)
        for (int t = tid; t < ITILE * NO * 32; t += NTHR) {
            int j  = t / (NO * 32);
            int r  = t - j * (NO * 32);
            int o  = r >> 5;
            int qg = r & 31;                       // global f4 index = d*2 + e4
            int qs = ((qg & 1) << 4) | (qg >> 1);  // shared index = e4*16 + d
            shW[(j * NO + o) * 32 + qs] = Wf4[(o * NI + i0 + j) * 32 + qg];
        }
        // Stage x[:, i0..i0+3, :]  (ITILE*64*2 float4 = 512 f4)
        for (int t = tid; t < ITILE * NB * 2; t += NTHR) {
            int j = t >> 7;
            int r = t & 127;
            int b = r >> 1;
            int q = r & 1;
            shx[(j * NB + b) * 2 + q] = xf4[((b * NI + i0 + j) << 1) + q];
        }
        __syncthreads();

        #pragma unroll
        for (int j = 0; j < ITILE; j++) {
            float4 xa0 = shx[(j * NB + b0) * 2 + 0];
            float4 xb0 = shx[(j * NB + b0) * 2 + 1];
            float4 xa1 = shx[(j * NB + b1) * 2 + 0];
            float4 xb1 = shx[(j * NB + b1) * 2 + 1];

            float u0[NO], u1[NO];
            #pragma unroll
            for (int o = 0; o < NO; o++) {
                float4 wa = shW[(j * NO + o) * 32 + lane];       // e = 0..3
                float4 wb = shW[(j * NO + o) * 32 + 16 + lane];  // e = 4..7
                u0[o] = wa.x * xa0.x + wa.y * xa0.y + wa.z * xa0.z + wa.w * xa0.w
                      + wb.x * xb0.x + wb.y * xb0.y + wb.z * xb0.z + wb.w * xb0.w;
                u1[o] = wa.x * xa1.x + wa.y * xa1.y + wa.z * xa1.z + wa.w * xa1.w
                      + wb.x * xb1.x + wb.y * xb1.y + wb.z * xb1.z + wb.w * xb1.w;
            }

            if (ITER == 0) {
                #pragma unroll
                for (int o = 0; o < NO; o++) { acc0[o] += u0[o]; acc1[o] += u1[o]; }
            } else {
                // agreement a[o] = sum_d u_hat[o][d] * v[o][d] across the 16 d-lanes
                float a0[NO], a1[NO];
                #pragma unroll
                for (int o = 0; o < NO; o++) {
                    float p = u0[o] * vr0[o];
                    p += __shfl_xor_sync(0xffffffffu, p, 8, 16);
                    p += __shfl_xor_sync(0xffffffffu, p, 4, 16);
                    p += __shfl_xor_sync(0xffffffffu, p, 2, 16);
                    p += __shfl_xor_sync(0xffffffffu, p, 1, 16);
                    a0[o] = p;
                    float q = u1[o] * vr1[o];
                    q += __shfl_xor_sync(0xffffffffu, q, 8, 16);
                    q += __shfl_xor_sync(0xffffffffu, q, 4, 16);
                    q += __shfl_xor_sync(0xffffffffu, q, 2, 16);
                    q += __shfl_xor_sync(0xffffffffu, q, 1, 16);
                    a1[o] = q;
                }
                // softmax over o (all 16 lanes of a group hold identical a[])
                float m0 = a0[0], m1 = a1[0];
                #pragma unroll
                for (int o = 1; o < NO; o++) { m0 = fmaxf(m0, a0[o]); m1 = fmaxf(m1, a1[o]); }
                float sum0 = 0.f, sum1 = 0.f;
                #pragma unroll
                for (int o = 0; o < NO; o++) {
                    a0[o] = __expf(a0[o] - m0); sum0 += a0[o];
                    a1[o] = __expf(a1[o] - m1); sum1 += a1[o];
                }
                float r0 = __fdividef(1.f, sum0);
                float r1 = __fdividef(1.f, sum1);
                #pragma unroll
                for (int o = 0; o < NO; o++) {
                    acc0[o] = fmaf(a0[o] * r0, u0[o], acc0[o]);
                    acc1[o] = fmaf(a1[o] * r1, u1[o], acc1[o]);
                }
            }
        }
    }

    #pragma unroll
    for (int o = 0; o < NO; o++) {
        atomicAdd(&g_s[(b0 * NO + o) * ND + lane], acc0[o]);
        atomicAdd(&g_s[(b1 * NO + o) * ND + lane], acc1[o]);
    }
}

// squash + bookkeeping: v = (|s|^2 / (1+|s|^2) / (|s|+1e-8)) * s per (b,o) row.
// Also zeros g_s for the next pass (and the next graph replay).
// mode 0: write v0 to g_v and g_vsum.  mode 1: write v1, g_vsum += v1.
// mode 2: write final v to out.
__global__ void squash_kernel(float prescale, int mode, float* __restrict__ out)
{
    int idx = blockIdx.x * blockDim.x + threadIdx.x;  // 0..10239, lane d = idx&15
    float val = g_s[idx] * prescale;
    g_s[idx] = 0.f;
    float n2 = val * val;
    n2 += __shfl_xor_sync(0xffffffffu, n2, 8, 16);
    n2 += __shfl_xor_sync(0xffffffffu, n2, 4, 16);
    n2 += __shfl_xor_sync(0xffffffffu, n2, 2, 16);
    n2 += __shfl_xor_sync(0xffffffffu, n2, 1, 16);
    float norm  = sqrtf(n2);
    float scale = n2 / ((1.f + n2) * (norm + 1e-8f));
    float v = scale * val;
    if (mode == 0)      { g_v[idx] = v; g_vsum[idx] = v; }
    else if (mode == 1) { g_v[idx] = v; g_vsum[idx] += v; }
    else                { out[idx] = v; }
}

extern "C" void kernel_launch(void* const* d_in, const int* in_sizes, int n_in,
                              void* d_out, int out_size)
{
    const float* x = (const float*)d_in[0];  // [64, 8000, 8]
    const float* W = (const float*)d_in[1];  // [10, 8000, 16, 8]
    float* out = (float*)d_out;              // [64, 10, 16]

    // iter 0: uniform routing (c = 1/10 folded into prescale)
    pass_kernel<0><<<NBLK, NTHR>>>(x, W);
    squash_kernel<<<20, 512>>>(0.1f, 0, out);
    // iter 1: c = softmax_o(u_hat . v0)
    pass_kernel<1><<<NBLK, NTHR>>>(x, W);
    squash_kernel<<<20, 512>>>(1.0f, 1, out);
    // iter 2: logits accumulate -> b2 = u_hat . (v0 + v1)
    pass_kernel<2><<<NBLK, NTHR>>>(x, W);
    squash_kernel<<<20, 512>>>(1.0f, 2, out);
}

// round 2
// speedup vs baseline: 1.0001x; 1.0001x over previous
#include <cuda_runtime.h>

#define NB 64
#define NO 10
#define NI 8000
#define ND 16
#define NE 8

#define ITILE 4
#define NTHR 512
#define NSTAGES (NI / ITILE)   // 2000 stages of 4 i's
#define NBLK 592               // grid-stride; ~4 stages per block

// Scratch in device globals (no allocation allowed). Zero-initialized at load;
// squash_kernel re-zeros g_s at the end of every full run, so graph replays
// are deterministic.
__device__ float g_s[NB * NO * ND] = {};
__device__ float g_v[NB * NO * ND] = {};
__device__ float g_vsum[NB * NO * ND] = {};

// One fused pass: recompute u_hat[b,o,i,d] tile-by-tile from W,x staged in
// shared, apply routing weights (uniform for ITER 0, softmax of u_hat.v for
// ITER 1/2), accumulate s[b,o,d] in registers, flush with atomics.
// Thread layout: lane = d (16), group = b (each group covers b and b+32),
// so W is read from shared once per i and reused for all 64 batches.
template <int ITER>
__global__ void __launch_bounds__(NTHR)
pass_kernel(const float* __restrict__ xg, const float* __restrict__ Wg)
{
    // shW layout per (j,o): float4 index qs = e4*16 + d  (conflict-free reads:
    // lanes d=0..15 stride 16B -> one 128B phase per 8 lanes)
    __shared__ float4 shW[ITILE * NO * 32];  // 20 KB
    __shared__ float4 shx[ITILE * NB * 2];   // 8 KB

    const int tid  = threadIdx.x;
    const int lane = tid & 15;   // d
    const int grp  = tid >> 4;   // 0..31
    const int b0 = grp, b1 = grp + 32;

    float vr0[NO], vr1[NO];
    if (ITER >= 1) {
        const float* vin = (ITER == 1) ? g_v : g_vsum;
        #pragma unroll
        for (int o = 0; o < NO; o++) {
            vr0[o] = vin[(b0 * NO + o) * ND + lane];
            vr1[o] = vin[(b1 * NO + o) * ND + lane];
        }
    }

    float acc0[NO], acc1[NO];
    #pragma unroll
    for (int o = 0; o < NO; o++) { acc0[o] = 0.f; acc1[o] = 0.f; }

    const float4* Wf4 = (const float4*)Wg;
    const float4* xf4 = (const float4*)xg;

    for (int st = blockIdx.x; st < NSTAGES; st += NBLK) {
        const int i0 = st * ITILE;
        __syncthreads();
        // Stage W[o, i0..i0+3, :, :]  (ITILE*10*32 float4 = 1280 f4)
        for (int t = tid; t < ITILE * NO * 32; t += NTHR) {
            int j  = t / (NO * 32);
            int r  = t - j * (NO * 32);
            int o  = r >> 5;
            int qg = r & 31;                       // global f4 index = d*2 + e4
            int qs = ((qg & 1) << 4) | (qg >> 1);  // shared index = e4*16 + d
            shW[(j * NO + o) * 32 + qs] = Wf4[(o * NI + i0 + j) * 32 + qg];
        }
        // Stage x[:, i0..i0+3, :]  (ITILE*64*2 float4 = 512 f4)
        for (int t = tid; t < ITILE * NB * 2; t += NTHR) {
            int j = t >> 7;
            int r = t & 127;
            int b = r >> 1;
            int q = r & 1;
            shx[(j * NB + b) * 2 + q] = xf4[((b * NI + i0 + j) << 1) + q];
        }
        __syncthreads();

        #pragma unroll
        for (int j = 0; j < ITILE; j++) {
            float4 xa0 = shx[(j * NB + b0) * 2 + 0];
            float4 xb0 = shx[(j * NB + b0) * 2 + 1];
            float4 xa1 = shx[(j * NB + b1) * 2 + 0];
            float4 xb1 = shx[(j * NB + b1) * 2 + 1];

            float u0[NO], u1[NO];
            #pragma unroll
            for (int o = 0; o < NO; o++) {
                float4 wa = shW[(j * NO + o) * 32 + lane];       // e = 0..3
                float4 wb = shW[(j * NO + o) * 32 + 16 + lane];  // e = 4..7
                u0[o] = wa.x * xa0.x + wa.y * xa0.y + wa.z * xa0.z + wa.w * xa0.w
                      + wb.x * xb0.x + wb.y * xb0.y + wb.z * xb0.z + wb.w * xb0.w;
                u1[o] = wa.x * xa1.x + wa.y * xa1.y + wa.z * xa1.z + wa.w * xa1.w
                      + wb.x * xb1.x + wb.y * xb1.y + wb.z * xb1.z + wb.w * xb1.w;
            }

            if (ITER == 0) {
                #pragma unroll
                for (int o = 0; o < NO; o++) { acc0[o] += u0[o]; acc1[o] += u1[o]; }
            } else {
                // agreement a[o] = sum_d u_hat[o][d] * v[o][d] across the 16 d-lanes
                float a0[NO], a1[NO];
                #pragma unroll
                for (int o = 0; o < NO; o++) {
                    float p = u0[o] * vr0[o];
                    p += __shfl_xor_sync(0xffffffffu, p, 8, 16);
                    p += __shfl_xor_sync(0xffffffffu, p, 4, 16);
                    p += __shfl_xor_sync(0xffffffffu, p, 2, 16);
                    p += __shfl_xor_sync(0xffffffffu, p, 1, 16);
                    a0[o] = p;
                    float q = u1[o] * vr1[o];
                    q += __shfl_xor_sync(0xffffffffu, q, 8, 16);
                    q += __shfl_xor_sync(0xffffffffu, q, 4, 16);
                    q += __shfl_xor_sync(0xffffffffu, q, 2, 16);
                    q += __shfl_xor_sync(0xffffffffu, q, 1, 16);
                    a1[o] = q;
                }
                // softmax over o (all 16 lanes of a group hold identical a[])
                float m0 = a0[0], m1 = a1[0];
                #pragma unroll
                for (int o = 1; o < NO; o++) { m0 = fmaxf(m0, a0[o]); m1 = fmaxf(m1, a1[o]); }
                float sum0 = 0.f, sum1 = 0.f;
                #pragma unroll
                for (int o = 0; o < NO; o++) {
                    a0[o] = __expf(a0[o] - m0); sum0 += a0[o];
                    a1[o] = __expf(a1[o] - m1); sum1 += a1[o];
                }
                float r0 = __fdividef(1.f, sum0);
                float r1 = __fdividef(1.f, sum1);
                #pragma unroll
                for (int o = 0; o < NO; o++) {
                    acc0[o] = fmaf(a0[o] * r0, u0[o], acc0[o]);
                    acc1[o] = fmaf(a1[o] * r1, u1[o], acc1[o]);
                }
            }
        }
    }

    #pragma unroll
    for (int o = 0; o < NO; o++) {
        atomicAdd(&g_s[(b0 * NO + o) * ND + lane], acc0[o]);
        atomicAdd(&g_s[(b1 * NO + o) * ND + lane], acc1[o]);
    }
}

// squash + bookkeeping: v = (|s|^2 / (1+|s|^2) / (|s|+1e-8)) * s per (b,o) row.
// Also zeros g_s for the next pass (and the next graph replay).
// mode 0: write v0 to g_v and g_vsum.  mode 1: write v1, g_vsum += v1.
// mode 2: write final v to out.
__global__ void squash_kernel(float prescale, int mode, float* __restrict__ out)
{
    int idx = blockIdx.x * blockDim.x + threadIdx.x;  // 0..10239, lane d = idx&15
    float val = g_s[idx] * prescale;
    g_s[idx] = 0.f;
    float n2 = val * val;
    n2 += __shfl_xor_sync(0xffffffffu, n2, 8, 16);
    n2 += __shfl_xor_sync(0xffffffffu, n2, 4, 16);
    n2 += __shfl_xor_sync(0xffffffffu, n2, 2, 16);
    n2 += __shfl_xor_sync(0xffffffffu, n2, 1, 16);
    float norm  = sqrtf(n2);
    float scale = n2 / ((1.f + n2) * (norm + 1e-8f));
    float v = scale * val;
    if (mode == 0)      { g_v[idx] = v; g_vsum[idx] = v; }
    else if (mode == 1) { g_v[idx] = v; g_vsum[idx] += v; }
    else                { out[idx] = v; }
}

extern "C" void kernel_launch(void* const* d_in, const int* in_sizes, int n_in,
                              void* d_out, int out_size)
{
    const float* x = (const float*)d_in[0];  // [64, 8000, 8]
    const float* W = (const float*)d_in[1];  // [10, 8000, 16, 8]
    float* out = (float*)d_out;              // [64, 10, 16]

    // iter 0: uniform routing (c = 1/10 folded into prescale)
    pass_kernel<0><<<NBLK, NTHR>>>(x, W);
    squash_kernel<<<20, 512>>>(0.1f, 0, out);
    // iter 1: c = softmax_o(u_hat . v0)
    pass_kernel<1><<<NBLK, NTHR>>>(x, W);
    squash_kernel<<<20, 512>>>(1.0f, 1, out);
    // iter 2: logits accumulate -> b2 = u_hat . (v0 + v1)
    pass_kernel<2><<<NBLK, NTHR>>>(x, W);
    squash_kernel<<<20, 512>>>(1.0f, 2, out);
}

// round 3
// speedup vs baseline: 1.0411x; 1.0410x over previous
#include <cuda_runtime.h>

#define NB 64
#define NO 10
#define NI 8000
#define ND 16
#define NE 8

#define ITILE 4
#define NTHR 512
#define NSTAGES (NI / ITILE)   // 2000 stages of 4 i's
#define NBLK 592               // grid-stride; ~4 stages per block

// Scratch (no allocation allowed). g_s zeroed by the fused squash each pass,
// g_ticket reset by the last block -> graph replays are deterministic.
__device__ float g_s[NB * NO * ND] = {};
__device__ float g_v[NB * NO * ND] = {};
__device__ float g_vsum[NB * NO * ND] = {};
__device__ unsigned int g_ticket = 0;

// ---- f32x2 packed math (sm_10x; ptxas won't auto-fuse, must be PTX) ----
__device__ __forceinline__ unsigned long long f2mul(unsigned long long a, unsigned long long b) {
    unsigned long long d;
    asm("mul.rn.f32x2 %0, %1, %2;" : "=l"(d) : "l"(a), "l"(b));
    return d;
}
__device__ __forceinline__ unsigned long long f2fma(unsigned long long a, unsigned long long b, unsigned long long c) {
    unsigned long long d;
    asm("fma.rn.f32x2 %0, %1, %2, %3;" : "=l"(d) : "l"(a), "l"(b), "l"(c));
    return d;
}
__device__ __forceinline__ float f2hadd(unsigned long long a) {
    float lo, hi;
    asm("mov.b64 {%0, %1}, %2;" : "=f"(lo), "=f"(hi) : "l"(a));
    return lo + hi;
}

// One fused pass: recompute u_hat tile-by-tile, route, accumulate s in regs,
// flush with atomics; LAST block performs squash (fused epilogue).
// Thread layout: lane = d (16), group = b-pair (b0 = grp, b1 = grp+32).
template <int ITER>
__global__ void __launch_bounds__(NTHR)
pass_kernel(const float* __restrict__ xg, const float* __restrict__ Wg,
            float* __restrict__ out)
{
    __shared__ float4 shW[ITILE * NO * 32];  // 20 KB, (j,o): idx = e4*16 + d
    __shared__ float4 shx[ITILE * NB * 2];   // 8 KB

    const int tid  = threadIdx.x;
    const int lane = tid & 15;   // d
    const int grp  = tid >> 4;   // 0..31
    const int b0 = grp, b1 = grp + 32;

    const bool s8 = (lane & 8) != 0;
    const bool s4 = (lane & 4) != 0;
    const bool s2 = (lane & 2) != 0;
    const bool s1 = (lane & 1) != 0;
    // lane g holds a[o(g)], o(g) = b0==0 ? 4*b1+2*b2+b3 : 8+b3
    // valid (no duplicate) lanes for the softmax denominator:
    const bool validLane = (!s1) || (!s2 && !s4);

    float vr0[NO], vr1[NO];
    if (ITER >= 1) {
        const float* vin = (ITER == 1) ? g_v : g_vsum;
        #pragma unroll
        for (int o = 0; o < NO; o++) {
            vr0[o] = vin[(b0 * NO + o) * ND + lane];
            vr1[o] = vin[(b1 * NO + o) * ND + lane];
        }
    }

    // ITER 0: packed accumulators (even/odd e-pair partial sums; hadd at end).
    unsigned long long accp0[NO], accp1[NO];
    float acc0[NO], acc1[NO];
    #pragma unroll
    for (int o = 0; o < NO; o++) {
        accp0[o] = 0ull; accp1[o] = 0ull; acc0[o] = 0.f; acc1[o] = 0.f;
    }

    const float4* Wf4 = (const float4*)Wg;
    const float4* xf4 = (const float4*)xg;
    const ulonglong2* shW2 = reinterpret_cast<const ulonglong2*>(shW);
    const ulonglong2* shx2 = reinterpret_cast<const ulonglong2*>(shx);

    for (int st = blockIdx.x; st < NSTAGES; st += NBLK) {
        const int i0 = st * ITILE;
        __syncthreads();
        for (int t = tid; t < ITILE * NO * 32; t += NTHR) {
            int j  = t / (NO * 32);
            int r  = t - j * (NO * 32);
            int o  = r >> 5;
            int qg = r & 31;                       // global f4 index = d*2 + e4
            int qs = ((qg & 1) << 4) | (qg >> 1);  // shared index = e4*16 + d
            shW[(j * NO + o) * 32 + qs] = Wf4[(o * NI + i0 + j) * 32 + qg];
        }
        for (int t = tid; t < ITILE * NB * 2; t += NTHR) {
            int j = t >> 7;
            int r = t & 127;
            int b = r >> 1;
            int q = r & 1;
            shx[(j * NB + b) * 2 + q] = xf4[((b * NI + i0 + j) << 1) + q];
        }
        __syncthreads();

        #pragma unroll
        for (int j = 0; j < ITILE; j++) {
            ulonglong2 xa0 = shx2[(j * NB + b0) * 2 + 0];  // b0: (e0,e1),(e2,e3)
            ulonglong2 xb0 = shx2[(j * NB + b0) * 2 + 1];  //     (e4,e5),(e6,e7)
            ulonglong2 xa1 = shx2[(j * NB + b1) * 2 + 0];
            ulonglong2 xb1 = shx2[(j * NB + b1) * 2 + 1];

            if (ITER == 0) {
                #pragma unroll
                for (int o = 0; o < NO; o++) {
                    ulonglong2 wa = shW2[(j * NO + o) * 32 + lane];       // e0..3
                    ulonglong2 wb = shW2[(j * NO + o) * 32 + 16 + lane];  // e4..7
                    accp0[o] = f2fma(wa.x, xa0.x, accp0[o]);
                    accp0[o] = f2fma(wa.y, xa0.y, accp0[o]);
                    accp0[o] = f2fma(wb.x, xb0.x, accp0[o]);
                    accp0[o] = f2fma(wb.y, xb0.y, accp0[o]);
                    accp1[o] = f2fma(wa.x, xa1.x, accp1[o]);
                    accp1[o] = f2fma(wa.y, xa1.y, accp1[o]);
                    accp1[o] = f2fma(wb.x, xb1.x, accp1[o]);
                    accp1[o] = f2fma(wb.y, xb1.y, accp1[o]);
                }
            } else {
                float u0[NO], u1[NO];
                #pragma unroll
                for (int o = 0; o < NO; o++) {
                    ulonglong2 wa = shW2[(j * NO + o) * 32 + lane];
                    ulonglong2 wb = shW2[(j * NO + o) * 32 + 16 + lane];
                    unsigned long long t0 = f2mul(wa.x, xa0.x);
                    t0 = f2fma(wa.y, xa0.y, t0);
                    t0 = f2fma(wb.x, xb0.x, t0);
                    t0 = f2fma(wb.y, xb0.y, t0);
                    u0[o] = f2hadd(t0);
                    unsigned long long t1 = f2mul(wa.x, xa1.x);
                    t1 = f2fma(wa.y, xa1.y, t1);
                    t1 = f2fma(wb.x, xb1.x, t1);
                    t1 = f2fma(wb.y, xb1.y, t1);
                    u1[o] = f2hadd(t1);
                }

                // Routing for each batch: pairing-tree reduction over the 16
                // d-lanes, then distributed softmax (1 exp per lane).
                #pragma unroll
                for (int bb = 0; bb < 2; bb++) {
                    const float* u  = bb ? u1 : u0;
                    const float* vr = bb ? vr1 : vr0;
                    float* acc = bb ? acc1 : acc0;

                    float p[NO];
                    #pragma unroll
                    for (int o = 0; o < NO; o++) p[o] = u[o] * vr[o];

                    // stage xor8: 5 array-pairs
                    float q[5];
                    #pragma unroll
                    for (int k = 0; k < 5; k++) {
                        float keep = s8 ? p[2 * k + 1] : p[2 * k];
                        float send = s8 ? p[2 * k] : p[2 * k + 1];
                        q[k] = keep + __shfl_xor_sync(0xffffffffu, send, 8, 16);
                    }
                    // stage xor4
                    float r0, r1, r2;
                    {
                        float keep = s4 ? q[1] : q[0];
                        float send = s4 ? q[0] : q[1];
                        r0 = keep + __shfl_xor_sync(0xffffffffu, send, 4, 16);
                    }
                    {
                        float keep = s4 ? q[3] : q[2];
                        float send = s4 ? q[2] : q[3];
                        r1 = keep + __shfl_xor_sync(0xffffffffu, send, 4, 16);
                    }
                    r2 = q[4] + __shfl_xor_sync(0xffffffffu, q[4], 4, 16);
                    // stage xor2
                    float t0, t1;
                    {
                        float keep = s2 ? r1 : r0;
                        float send = s2 ? r0 : r1;
                        t0 = keep + __shfl_xor_sync(0xffffffffu, send, 2, 16);
                    }
                    t1 = r2 + __shfl_xor_sync(0xffffffffu, r2, 2, 16);
                    // stage xor1: lane holds its a[o(lane)]
                    float a;
                    {
                        float keep = s1 ? t1 : t0;
                        float send = s1 ? t0 : t1;
                        a = keep + __shfl_xor_sync(0xffffffffu, send, 1, 16);
                    }

                    // distributed softmax (logits tiny -> no max subtraction)
                    float e = __expf(a);
                    float m = validLane ? e : 0.f;
                    m += __shfl_xor_sync(0xffffffffu, m, 8, 16);
                    m += __shfl_xor_sync(0xffffffffu, m, 4, 16);
                    m += __shfl_xor_sync(0xffffffffu, m, 2, 16);
                    m += __shfl_xor_sync(0xffffffffu, m, 1, 16);
                    float c_self = __fdividef(e, m);

                    // broadcast c[o] from its owner lane, accumulate
                    // o -> lane: {0,8,4,12,2,10,6,14,1,9}
                    acc[0] = fmaf(__shfl_sync(0xffffffffu, c_self, 0, 16),  u[0], acc[0]);
                    acc[1] = fmaf(__shfl_sync(0xffffffffu, c_self, 8, 16),  u[1], acc[1]);
                    acc[2] = fmaf(__shfl_sync(0xffffffffu, c_self, 4, 16),  u[2], acc[2]);
                    acc[3] = fmaf(__shfl_sync(0xffffffffu, c_self, 12, 16), u[3], acc[3]);
                    acc[4] = fmaf(__shfl_sync(0xffffffffu, c_self, 2, 16),  u[4], acc[4]);
                    acc[5] = fmaf(__shfl_sync(0xffffffffu, c_self, 10, 16), u[5], acc[5]);
                    acc[6] = fmaf(__shfl_sync(0xffffffffu, c_self, 6, 16),  u[6], acc[6]);
                    acc[7] = fmaf(__shfl_sync(0xffffffffu, c_self, 14, 16), u[7], acc[7]);
                    acc[8] = fmaf(__shfl_sync(0xffffffffu, c_self, 1, 16),  u[8], acc[8]);
                    acc[9] = fmaf(__shfl_sync(0xffffffffu, c_self, 9, 16),  u[9], acc[9]);
                }
            }
        }
    }

    if (ITER == 0) {
        #pragma unroll
        for (int o = 0; o < NO; o++) {
            acc0[o] = f2hadd(accp0[o]);
            acc1[o] = f2hadd(accp1[o]);
        }
    }
    #pragma unroll
    for (int o = 0; o < NO; o++) {
        atomicAdd(&g_s[(b0 * NO + o) * ND + lane], acc0[o]);
        atomicAdd(&g_s[(b1 * NO + o) * ND + lane], acc1[o]);
    }

    // ---- fused squash: last block to finish does the epilogue ----
    __threadfence();
    __shared__ unsigned int lastFlag;
    if (tid == 0)
        lastFlag = (atomicAdd(&g_ticket, 1u) == (unsigned)(gridDim.x - 1)) ? 1u : 0u;
    __syncthreads();
    if (!lastFlag) return;
    __threadfence();  // acquire: all other blocks' atomics are visible

    const float prescale = (ITER == 0) ? 0.1f : 1.0f;
    #pragma unroll
    for (int k = 0; k < (NB * NO * ND) / NTHR; k++) {
        int idx = k * NTHR + tid;            // idx & 15 == lane (NTHR % 16 == 0)
        float val = g_s[idx] * prescale;
        g_s[idx] = 0.f;
        float n2 = val * val;
        n2 += __shfl_xor_sync(0xffffffffu, n2, 8, 16);
        n2 += __shfl_xor_sync(0xffffffffu, n2, 4, 16);
        n2 += __shfl_xor_sync(0xffffffffu, n2, 2, 16);
        n2 += __shfl_xor_sync(0xffffffffu, n2, 1, 16);
        float norm  = sqrtf(n2);
        float scale = n2 / ((1.f + n2) * (norm + 1e-8f));
        float v = scale * val;
        if (ITER == 0)      { g_v[idx] = v; g_vsum[idx] = v; }
        else if (ITER == 1) { g_v[idx] = v; g_vsum[idx] += v; }
        else                { out[idx] = v; }
    }
    if (tid == 0) g_ticket = 0;  // reset for next pass / next graph replay
}

extern "C" void kernel_launch(void* const* d_in, const int* in_sizes, int n_in,
                              void* d_out, int out_size)
{
    const float* x = (const float*)d_in[0];  // [64, 8000, 8]
    const float* W = (const float*)d_in[1];  // [10, 8000, 16, 8]
    float* out = (float*)d_out;              // [64, 10, 16]

    pass_kernel<0><<<NBLK, NTHR>>>(x, W, out);  // uniform c=0.1 (in prescale)
    pass_kernel<1><<<NBLK, NTHR>>>(x, W, out);  // c = softmax_o(u.v0)
    pass_kernel<2><<<NBLK, NTHR>>>(x, W, out);  // c = softmax_o(u.(v0+v1))
}